// round 2
// baseline (speedup 1.0000x reference)
#include <cuda_runtime.h>
#include <cuda_fp16.h>

// ----------------------------------------------------------------------------
// Packed bidirectional 2-layer LSTM.
//   inputs : input(total,256) f32, batch_sizes(T) i32, h0(4,64,128), c0(4,64,128),
//            W_ih(4,512,256), W_hh(4,512,128), b_ih(4,512), b_hh(4,512)
//   outputs: packed_out(total,256) | h_n(4,64,128) | c_n(4,64,128)  (concatenated)
// ----------------------------------------------------------------------------

#define TOTAL_MAX 49408
#define TMAX      1024

// scratch (device globals: no allocation allowed)
__device__ float g_gpre[2 * TOTAL_MAX * 512];          // gate preacts, both dirs of current layer (~202MB)
__device__ float g_out1[TOTAL_MAX * 256];              // layer-1 output (fwd||bwd), packed (~50MB)
__device__ int   g_offsets[TMAX];
__device__ int   g_len[64];

// ---------------------------------------------------------------- setup -----
__global__ void setup_kernel(const int* __restrict__ bs, int T)
{
    __shared__ int s[TMAX];
    int tid = threadIdx.x;
    if (tid < T) s[tid] = bs[tid];
    __syncthreads();
    if (tid == 0) {
        int off = 0;
        for (int t = 0; t < T; ++t) { g_offsets[t] = off; off += s[t]; }
    }
    if (tid < 64) {
        int c = 0;
        for (int t = 0; t < T; ++t) c += (s[t] > tid) ? 1 : 0;
        g_len[tid] = c;
    }
}

// ----------------------------------------------------------------- gemm -----
// C[dir][tok][g] = A[tok,:] . W[(2l+dir)][g][:] + bih + bhh
// A is (total,256); W rows (1024,256) for this layer (dir-major). Tiles 128x64xK256.
__global__ __launch_bounds__(256)
void gemm_kernel(const float* __restrict__ x_in,
                 const float* __restrict__ Wih_all,
                 const float* __restrict__ bih_all,
                 const float* __restrict__ bhh_all,
                 int total, int layer)
{
    __shared__ float As[32][132];
    __shared__ float Bs[32][68];

    const float* A  = (layer == 0) ? x_in : g_out1;
    const float* W  = Wih_all + (size_t)layer * 262144;   // layer * 2*512*256
    const float* bi = bih_all + layer * 1024;
    const float* bh = bhh_all + layer * 1024;

    const int tid   = threadIdx.x;
    const int mBase = blockIdx.x * 128;
    const int nBase = blockIdx.y * 64;
    const int tx = tid & 15;         // n / 4
    const int ty = tid >> 4;         // m / 8

    float acc[8][4];
#pragma unroll
    for (int i = 0; i < 8; ++i)
#pragma unroll
        for (int j = 0; j < 4; ++j) acc[i][j] = 0.f;

    for (int k0 = 0; k0 < 256; k0 += 32) {
#pragma unroll
        for (int r = 0; r < 4; ++r) {
            int idx = tid + r * 256;
            int m = idx >> 3, q = idx & 7;
            int row = mBase + m;
            float4 v = make_float4(0.f, 0.f, 0.f, 0.f);
            if (row < total)
                v = *reinterpret_cast<const float4*>(&A[(size_t)row * 256 + k0 + q * 4]);
            As[q * 4 + 0][m] = v.x;
            As[q * 4 + 1][m] = v.y;
            As[q * 4 + 2][m] = v.z;
            As[q * 4 + 3][m] = v.w;
        }
#pragma unroll
        for (int r = 0; r < 2; ++r) {
            int idx = tid + r * 256;
            int n = idx >> 3, q = idx & 7;
            float4 v = *reinterpret_cast<const float4*>(&W[(size_t)(nBase + n) * 256 + k0 + q * 4]);
            Bs[q * 4 + 0][n] = v.x;
            Bs[q * 4 + 1][n] = v.y;
            Bs[q * 4 + 2][n] = v.z;
            Bs[q * 4 + 3][n] = v.w;
        }
        __syncthreads();

#pragma unroll
        for (int k = 0; k < 32; ++k) {
            float4 a0 = *reinterpret_cast<const float4*>(&As[k][ty * 8]);
            float4 a1 = *reinterpret_cast<const float4*>(&As[k][ty * 8 + 4]);
            float4 b0 = *reinterpret_cast<const float4*>(&Bs[k][tx * 4]);
            float am[8] = {a0.x, a0.y, a0.z, a0.w, a1.x, a1.y, a1.z, a1.w};
            float bn[4] = {b0.x, b0.y, b0.z, b0.w};
#pragma unroll
            for (int i = 0; i < 8; ++i)
#pragma unroll
                for (int j = 0; j < 4; ++j)
                    acc[i][j] = fmaf(am[i], bn[j], acc[i][j]);
        }
        __syncthreads();
    }

#pragma unroll
    for (int i = 0; i < 8; ++i) {
        int tok = mBase + ty * 8 + i;
        if (tok >= total) continue;
#pragma unroll
        for (int j = 0; j < 4; ++j) {
            int gg  = nBase + tx * 4 + j;
            int dir = gg >> 9;
            int g   = gg & 511;
            g_gpre[((size_t)dir * total + tok) * 512 + g] = acc[i][j] + bi[gg] + bh[gg];
        }
    }
}

// ------------------------------------------------------------- recurrence ---
__device__ __forceinline__ float sigf(float x)
{
    return __fdividef(1.0f, 1.0f + __expf(-x));
}
__device__ __forceinline__ float tanhfast(float x)
{
    x = fminf(fmaxf(x, -12.0f), 12.0f);
    float e = __expf(2.0f * x);
    return __fdividef(e - 1.0f, e + 1.0f);
}

// 128 CTAs: blockIdx.x = dir*64 + b. 512 threads: thread = gate index.
// W_hh held in SMEM as fp16 pairs, k-pair-major (conflict-free LDS). fp32 accum.
__global__ __launch_bounds__(512, 1)
void rec_kernel(const float* __restrict__ Whh_all,
                const float* __restrict__ h0,
                const float* __restrict__ c0,
                float* __restrict__ dout,
                int total, int T, int layer)
{
    extern __shared__ char smem[];
    __half2* wp  = reinterpret_cast<__half2*>(smem);            // [64][512] -> 128KB
    float*   hs  = reinterpret_cast<float*>(smem + 131072);     // 128 f32
    float*   zs  = hs + 128;                                    // 512 f32
    int*     offs = reinterpret_cast<int*>(zs + 512);           // T ints

    const int tid = threadIdx.x;
    const int dir = blockIdx.x >> 6;
    const int b   = blockIdx.x & 63;
    const int kix = 2 * layer + dir;

    const float* gpd = g_gpre + (size_t)dir * (size_t)total * 512;
    const float* W   = Whh_all + (size_t)kix * 512 * 128;
    float* outb = (layer == 0) ? g_out1 : dout;

    for (int i = tid; i < T; i += 512) offs[i] = g_offsets[i];

    // W[g][k] -> wp[kp*512 + g] = (W[g][2kp], W[g][2kp+1]) in fp16
    for (int i = tid; i < 512 * 64; i += 512) {
        int kp = i >> 9;       // 0..63
        int g  = i & 511;
        float2 wv = *reinterpret_cast<const float2*>(&W[g * 128 + kp * 2]);
        wp[kp * 512 + g] = __floats2half2_rn(wv.x, wv.y);
    }

    float creg = 0.f;
    if (tid < 128) {
        hs[tid] = h0[(size_t)kix * 8192 + b * 128 + tid];
        creg    = c0[(size_t)kix * 8192 + b * 128 + tid];
    }
    __syncthreads();

    const int  len = g_len[b];
    const bool fwd = (dir == 0);

    int   tok  = offs[fwd ? 0 : (len - 1)] + b;
    float gcur = gpd[(size_t)tok * 512 + tid];

    const __half2* wrow = wp + tid;
    const float4*  hs4  = reinterpret_cast<const float4*>(hs);

    for (int s = 0; s < len; ++s) {
        // prefetch next step's gate preactivation (hides dependent LDG latency)
        int   toknext = 0;
        float gnext   = 0.f;
        if (s + 1 < len) {
            int tn  = fwd ? (s + 1) : (len - 2 - s);
            toknext = offs[tn] + b;
            gnext   = gpd[(size_t)toknext * 512 + tid];
        }

        float acc0 = gcur, acc1 = 0.f;
#pragma unroll
        for (int kk = 0; kk < 16; ++kk) {
            float4 ha = hs4[kk * 2];
            float4 hb = hs4[kk * 2 + 1];
            float2 f0 = __half22float2(wrow[(kk * 4 + 0) * 512]);
            float2 f1 = __half22float2(wrow[(kk * 4 + 1) * 512]);
            float2 f2 = __half22float2(wrow[(kk * 4 + 2) * 512]);
            float2 f3 = __half22float2(wrow[(kk * 4 + 3) * 512]);
            acc0 = fmaf(f0.x, ha.x, acc0);
            acc1 = fmaf(f0.y, ha.y, acc1);
            acc0 = fmaf(f1.x, ha.z, acc0);
            acc1 = fmaf(f1.y, ha.w, acc1);
            acc0 = fmaf(f2.x, hb.x, acc0);
            acc1 = fmaf(f2.y, hb.y, acc1);
            acc0 = fmaf(f3.x, hb.z, acc0);
            acc1 = fmaf(f3.y, hb.w, acc1);
        }
        zs[tid] = acc0 + acc1;
        __syncthreads();

        if (tid < 128) {
            float zi = zs[tid];
            float zf = zs[tid + 128];
            float zg = zs[tid + 256];
            float zo = zs[tid + 384];
            float ig = sigf(zi);
            float fg = sigf(zf);
            float gv = tanhfast(zg);
            float og = sigf(zo);
            creg = fg * creg + ig * gv;
            float hv = og * tanhfast(creg);
            hs[tid] = hv;
            outb[(size_t)tok * 256 + dir * 128 + tid] = hv;
        }
        __syncthreads();

        gcur = gnext;
        tok  = toknext;
    }

    if (tid < 128) {
        float* hn = dout + (size_t)total * 256 + (size_t)kix * 8192 + (size_t)b * 128;
        float* cn = hn + 4 * 64 * 128;
        hn[tid] = hs[tid];
        cn[tid] = creg;
    }
}

// ---------------------------------------------------------------- launch ----
extern "C" void kernel_launch(void* const* d_in, const int* in_sizes, int n_in,
                              void* d_out, int out_size)
{
    const float* input       = (const float*)d_in[0];
    const int*   batch_sizes = (const int*)  d_in[1];
    const float* h0          = (const float*)d_in[2];
    const float* c0          = (const float*)d_in[3];
    const float* W_ih        = (const float*)d_in[4];
    const float* W_hh        = (const float*)d_in[5];
    const float* b_ih        = (const float*)d_in[6];
    const float* b_hh        = (const float*)d_in[7];
    float* out = (float*)d_out;

    int T     = in_sizes[1];
    int total = in_sizes[0] / 256;
    if (total > TOTAL_MAX) total = TOTAL_MAX;
    if (T > TMAX) T = TMAX;

    const int REC_SMEM = 131072 + 128 * 4 + 512 * 4 + TMAX * 4;  // 137728 B
    cudaFuncSetAttribute(rec_kernel, cudaFuncAttributeMaxDynamicSharedMemorySize, REC_SMEM);

    setup_kernel<<<1, 1024>>>(batch_sizes, T);

    dim3 ggrid((total + 127) / 128, 16);
    // layer 0
    gemm_kernel<<<ggrid, 256>>>(input, W_ih, b_ih, b_hh, total, 0);
    rec_kernel<<<128, 512, REC_SMEM>>>(W_hh, h0, c0, out, total, T, 0);
    // layer 1
    gemm_kernel<<<ggrid, 256>>>(input, W_ih, b_ih, b_hh, total, 1);
    rec_kernel<<<128, 512, REC_SMEM>>>(W_hh, h0, c0, out, total, T, 1);
}

// round 3
// speedup vs baseline: 1.1883x; 1.1883x over previous
#include <cuda_runtime.h>
#include <cuda_fp16.h>

// ----------------------------------------------------------------------------
// Packed bidirectional 2-layer LSTM.
//   inputs : input(total,256) f32, batch_sizes(T) i32, h0(4,64,128), c0(4,64,128),
//            W_ih(4,512,256), W_hh(4,512,128), b_ih(4,512), b_hh(4,512)
//   outputs: packed_out(total,256) | h_n(4,64,128) | c_n(4,64,128)  (concatenated)
// ----------------------------------------------------------------------------

#define TOTAL_MAX 49408
#define TMAX      1024

// scratch (device globals: no allocation allowed)
__device__ float g_gpre[2 * TOTAL_MAX * 512];          // gate preacts, both dirs of current layer
__device__ float g_out1[TOTAL_MAX * 256];              // layer-1 output (fwd||bwd), packed
__device__ int   g_offsets[TMAX];
__device__ int   g_len[64];

// ---------------------------------------------------------------- setup -----
__global__ void setup_kernel(const int* __restrict__ bs, int T)
{
    __shared__ int s[TMAX];
    int tid = threadIdx.x;
    if (tid < T) s[tid] = bs[tid];
    __syncthreads();
    if (tid == 0) {
        int off = 0;
        for (int t = 0; t < T; ++t) { g_offsets[t] = off; off += s[t]; }
    }
    if (tid < 64) {
        int c = 0;
        for (int t = 0; t < T; ++t) c += (s[t] > tid) ? 1 : 0;
        g_len[tid] = c;
    }
}

// ----------------------------------------------------------------- gemm -----
// C[dir][tok][g] = A[tok,:] . W[(2l+dir)][g][:] + bih + bhh
__global__ __launch_bounds__(256)
void gemm_kernel(const float* __restrict__ x_in,
                 const float* __restrict__ Wih_all,
                 const float* __restrict__ bih_all,
                 const float* __restrict__ bhh_all,
                 int total, int layer)
{
    __shared__ float As[32][132];
    __shared__ float Bs[32][68];

    const float* A  = (layer == 0) ? x_in : g_out1;
    const float* W  = Wih_all + (size_t)layer * 262144;
    const float* bi = bih_all + layer * 1024;
    const float* bh = bhh_all + layer * 1024;

    const int tid   = threadIdx.x;
    const int mBase = blockIdx.x * 128;
    const int nBase = blockIdx.y * 64;
    const int tx = tid & 15;
    const int ty = tid >> 4;

    float acc[8][4];
#pragma unroll
    for (int i = 0; i < 8; ++i)
#pragma unroll
        for (int j = 0; j < 4; ++j) acc[i][j] = 0.f;

    for (int k0 = 0; k0 < 256; k0 += 32) {
#pragma unroll
        for (int r = 0; r < 4; ++r) {
            int idx = tid + r * 256;
            int m = idx >> 3, q = idx & 7;
            int row = mBase + m;
            float4 v = make_float4(0.f, 0.f, 0.f, 0.f);
            if (row < total)
                v = *reinterpret_cast<const float4*>(&A[(size_t)row * 256 + k0 + q * 4]);
            As[q * 4 + 0][m] = v.x;
            As[q * 4 + 1][m] = v.y;
            As[q * 4 + 2][m] = v.z;
            As[q * 4 + 3][m] = v.w;
        }
#pragma unroll
        for (int r = 0; r < 2; ++r) {
            int idx = tid + r * 256;
            int n = idx >> 3, q = idx & 7;
            float4 v = *reinterpret_cast<const float4*>(&W[(size_t)(nBase + n) * 256 + k0 + q * 4]);
            Bs[q * 4 + 0][n] = v.x;
            Bs[q * 4 + 1][n] = v.y;
            Bs[q * 4 + 2][n] = v.z;
            Bs[q * 4 + 3][n] = v.w;
        }
        __syncthreads();

#pragma unroll
        for (int k = 0; k < 32; ++k) {
            float4 a0 = *reinterpret_cast<const float4*>(&As[k][ty * 8]);
            float4 a1 = *reinterpret_cast<const float4*>(&As[k][ty * 8 + 4]);
            float4 b0 = *reinterpret_cast<const float4*>(&Bs[k][tx * 4]);
            float am[8] = {a0.x, a0.y, a0.z, a0.w, a1.x, a1.y, a1.z, a1.w};
            float bn[4] = {b0.x, b0.y, b0.z, b0.w};
#pragma unroll
            for (int i = 0; i < 8; ++i)
#pragma unroll
                for (int j = 0; j < 4; ++j)
                    acc[i][j] = fmaf(am[i], bn[j], acc[i][j]);
        }
        __syncthreads();
    }

#pragma unroll
    for (int i = 0; i < 8; ++i) {
        int tok = mBase + ty * 8 + i;
        if (tok >= total) continue;
#pragma unroll
        for (int j = 0; j < 4; ++j) {
            int gg  = nBase + tx * 4 + j;
            int dir = gg >> 9;
            int g   = gg & 511;
            g_gpre[((size_t)dir * total + tok) * 512 + g] = acc[i][j] + bi[gg] + bh[gg];
        }
    }
}

// ------------------------------------------------------------- recurrence ---
__device__ __forceinline__ float sigf(float x)
{
    return __fdividef(1.0f, 1.0f + __expf(-x));
}
__device__ __forceinline__ float tanhfast(float x)
{
    x = fminf(fmaxf(x, -12.0f), 12.0f);
    float e = __expf(2.0f * x);
    return __fdividef(e - 1.0f, e + 1.0f);
}

// packed f32x2 FMA (Blackwell FFMA2): d = a*b + c elementwise on f32 pairs
__device__ __forceinline__ unsigned long long ffma2(unsigned long long a,
                                                    unsigned long long b,
                                                    unsigned long long c)
{
    unsigned long long d;
    asm("fma.rn.f32x2 %0, %1, %2, %3;" : "=l"(d) : "l"(a), "l"(b), "l"(c));
    return d;
}
__device__ __forceinline__ unsigned long long packf2(float lo, float hi)
{
    unsigned long long r;
    asm("mov.b64 %0, {%1, %2};" : "=l"(r) : "f"(lo), "f"(hi));
    return r;
}
__device__ __forceinline__ float2 unpackf2(unsigned long long v)
{
    float2 f;
    asm("mov.b64 {%0, %1}, %2;" : "=f"(f.x), "=f"(f.y) : "l"(v));
    return f;
}

// 128 CTAs: blockIdx.x = dir*64 + b. 512 threads: thread = gate index.
// W_hh: k<64 in fp32 register pairs, k>=64 in SMEM fp16 quads. f32x2 FMA.
__global__ __launch_bounds__(512, 1)
void rec_kernel(const float* __restrict__ Whh_all,
                const float* __restrict__ h0,
                const float* __restrict__ c0,
                float* __restrict__ dout,
                int total, int T, int layer)
{
    extern __shared__ char smem[];
    uint2* wq = reinterpret_cast<uint2*>(smem);                // [16][512] quads of k>=64 -> 64KB
    float* hs = reinterpret_cast<float*>(smem + 65536);        // 128 f32 (16B aligned)
    float* zs = hs + 128;                                      // 512 f32
    int* offs = reinterpret_cast<int*>(zs + 512);              // T ints

    const int tid = threadIdx.x;
    const int dir = blockIdx.x >> 6;
    const int b   = blockIdx.x & 63;
    const int kix = 2 * layer + dir;

    const float* gpd = g_gpre + (size_t)dir * (size_t)total * 512;
    const float* W   = Whh_all + (size_t)kix * 512 * 128;
    float* outb = (layer == 0) ? g_out1 : dout;

    for (int i = tid; i < T; i += 512) offs[i] = g_offsets[i];

    // k >= 64 weights -> SMEM fp16 quads: wq[kq*512 + g] = (h2(k0,k1), h2(k2,k3))
    for (int i = tid; i < 512 * 16; i += 512) {
        int kq = i >> 9;       // 0..15
        int g  = i & 511;
        float4 wv = *reinterpret_cast<const float4*>(&W[g * 128 + 64 + kq * 4]);
        __half2 lo = __floats2half2_rn(wv.x, wv.y);
        __half2 hi = __floats2half2_rn(wv.z, wv.w);
        uint2 u;
        u.x = *reinterpret_cast<unsigned int*>(&lo);
        u.y = *reinterpret_cast<unsigned int*>(&hi);
        wq[kq * 512 + g] = u;
    }

    // k < 64 weights -> registers as f32x2 pairs (32 x 64-bit regs)
    unsigned long long wr[32];
#pragma unroll
    for (int p = 0; p < 32; ++p) {
        float2 wv = *reinterpret_cast<const float2*>(&W[tid * 128 + 2 * p]);
        wr[p] = packf2(wv.x, wv.y);
    }

    float creg = 0.f;
    if (tid < 128) {
        hs[tid] = h0[(size_t)kix * 8192 + b * 128 + tid];
        creg    = c0[(size_t)kix * 8192 + b * 128 + tid];
    }
    __syncthreads();

    const int  len = g_len[b];
    const bool fwd = (dir == 0);

    int   tok  = offs[fwd ? 0 : (len - 1)] + b;
    float gcur = gpd[(size_t)tok * 512 + tid];

    const double2* h2p = reinterpret_cast<const double2*>(hs);   // pairs of f32x2

    for (int s = 0; s < len; ++s) {
        // prefetch next step's gate preactivation (hides dependent LDG latency)
        int   toknext = 0;
        float gnext   = 0.f;
        if (s + 1 < len) {
            int tn  = fwd ? (s + 1) : (len - 2 - s);
            toknext = offs[tn] + b;
            gnext   = gpd[(size_t)toknext * 512 + tid];
        }

        unsigned long long accA = 0ull, accB = 0ull;

        // k < 64: weights from registers
#pragma unroll
        for (int q = 0; q < 16; ++q) {
            double2 h2 = h2p[q];                     // broadcast LDS.128 (4 k-values)
            accA = ffma2(wr[2 * q],     __double_as_longlong(h2.x), accA);
            accB = ffma2(wr[2 * q + 1], __double_as_longlong(h2.y), accB);
        }
        // k >= 64: weights from SMEM fp16
#pragma unroll
        for (int q = 0; q < 16; ++q) {
            uint2 wv = wq[q * 512 + tid];            // conflict-free LDS.64
            double2 h2 = h2p[16 + q];
            float2 f0 = __half22float2(*reinterpret_cast<__half2*>(&wv.x));
            float2 f1 = __half22float2(*reinterpret_cast<__half2*>(&wv.y));
            accA = ffma2(packf2(f0.x, f0.y), __double_as_longlong(h2.x), accA);
            accB = ffma2(packf2(f1.x, f1.y), __double_as_longlong(h2.y), accB);
        }

        float2 fa = unpackf2(accA);
        float2 fb = unpackf2(accB);
        zs[tid] = gcur + (fa.x + fa.y) + (fb.x + fb.y);
        __syncthreads();

        if (tid < 128) {
            float zi = zs[tid];
            float zf = zs[tid + 128];
            float zg = zs[tid + 256];
            float zo = zs[tid + 384];
            float ig = sigf(zi);
            float fg = sigf(zf);
            float gv = tanhfast(zg);
            float og = sigf(zo);
            creg = fg * creg + ig * gv;
            float hv = og * tanhfast(creg);
            hs[tid] = hv;
            outb[(size_t)tok * 256 + dir * 128 + tid] = hv;
        }
        __syncthreads();

        gcur = gnext;
        tok  = toknext;
    }

    if (tid < 128) {
        float* hn = dout + (size_t)total * 256 + (size_t)kix * 8192 + (size_t)b * 128;
        float* cn = hn + 4 * 64 * 128;
        hn[tid] = hs[tid];
        cn[tid] = creg;
    }
}

// ---------------------------------------------------------------- launch ----
extern "C" void kernel_launch(void* const* d_in, const int* in_sizes, int n_in,
                              void* d_out, int out_size)
{
    const float* input       = (const float*)d_in[0];
    const int*   batch_sizes = (const int*)  d_in[1];
    const float* h0          = (const float*)d_in[2];
    const float* c0          = (const float*)d_in[3];
    const float* W_ih        = (const float*)d_in[4];
    const float* W_hh        = (const float*)d_in[5];
    const float* b_ih        = (const float*)d_in[6];
    const float* b_hh        = (const float*)d_in[7];
    float* out = (float*)d_out;

    int T     = in_sizes[1];
    int total = in_sizes[0] / 256;
    if (total > TOTAL_MAX) total = TOTAL_MAX;
    if (T > TMAX) T = TMAX;

    const int REC_SMEM = 65536 + 128 * 4 + 512 * 4 + TMAX * 4;  // 72192 B
    cudaFuncSetAttribute(rec_kernel, cudaFuncAttributeMaxDynamicSharedMemorySize, REC_SMEM);

    setup_kernel<<<1, 1024>>>(batch_sizes, T);

    dim3 ggrid((total + 127) / 128, 16);
    // layer 0
    gemm_kernel<<<ggrid, 256>>>(input, W_ih, b_ih, b_hh, total, 0);
    rec_kernel<<<128, 512, REC_SMEM>>>(W_hh, h0, c0, out, total, T, 0);
    // layer 1
    gemm_kernel<<<ggrid, 256>>>(input, W_ih, b_ih, b_hh, total, 1);
    rec_kernel<<<128, 512, REC_SMEM>>>(W_hh, h0, c0, out, total, T, 1);
}

// round 4
// speedup vs baseline: 1.4298x; 1.2032x over previous
#include <cuda_runtime.h>
#include <cuda_fp16.h>

// ----------------------------------------------------------------------------
// Packed bidirectional 2-layer LSTM.
//   inputs : input(total,256) f32, batch_sizes(T) i32, h0(4,64,128), c0(4,64,128),
//            W_ih(4,512,256), W_hh(4,512,128), b_ih(4,512), b_hh(4,512)
//   outputs: packed_out(total,256) | h_n(4,64,128) | c_n(4,64,128)
// ----------------------------------------------------------------------------

#define TOTAL_MAX 49408
#define TMAX      1024

__device__ float g_gpre[2 * TOTAL_MAX * 512];
__device__ float g_out1[TOTAL_MAX * 256];
__device__ int   g_offsets[TMAX];
__device__ int   g_len[64];

typedef unsigned long long ull;

__device__ __forceinline__ ull ffma2(ull a, ull b, ull c)
{
    ull d;
    asm("fma.rn.f32x2 %0, %1, %2, %3;" : "=l"(d) : "l"(a), "l"(b), "l"(c));
    return d;
}
__device__ __forceinline__ ull packf2(float lo, float hi)
{
    ull r;
    asm("mov.b64 %0, {%1, %2};" : "=l"(r) : "f"(lo), "f"(hi));
    return r;
}
__device__ __forceinline__ float2 unpackf2(ull v)
{
    float2 f;
    asm("mov.b64 {%0, %1}, %2;" : "=f"(f.x), "=f"(f.y) : "l"(v));
    return f;
}
__device__ __forceinline__ __half2 uh2(unsigned int u)
{
    return *reinterpret_cast<__half2*>(&u);
}

// ---------------------------------------------------------------- setup -----
__global__ void setup_kernel(const int* __restrict__ bs, int T)
{
    __shared__ int s[TMAX];
    int tid = threadIdx.x;
    if (tid < T) s[tid] = bs[tid];
    __syncthreads();
    if (tid == 0) {
        int off = 0;
        for (int t = 0; t < T; ++t) { g_offsets[t] = off; off += s[t]; }
    }
    if (tid < 64) {
        int c = 0;
        for (int t = 0; t < T; ++t) c += (s[t] > tid) ? 1 : 0;
        g_len[tid] = c;
    }
}

// ----------------------------------------------------------------- gemm -----
// f32x2 version: acc over (m-pair, n). a pairs natural from As; b duplicated
// via mov (alu pipe, overlaps fma pipe).
__global__ __launch_bounds__(256)
void gemm_kernel(const float* __restrict__ x_in,
                 const float* __restrict__ Wih_all,
                 const float* __restrict__ bih_all,
                 const float* __restrict__ bhh_all,
                 int total, int layer)
{
    __shared__ float As[32][132];
    __shared__ float Bs[32][68];

    const float* A  = (layer == 0) ? x_in : g_out1;
    const float* W  = Wih_all + (size_t)layer * 262144;
    const float* bi = bih_all + layer * 1024;
    const float* bh = bhh_all + layer * 1024;

    const int tid   = threadIdx.x;
    const int mBase = blockIdx.x * 128;
    const int nBase = blockIdx.y * 64;
    const int tx = tid & 15;
    const int ty = tid >> 4;

    ull acc[4][4];
#pragma unroll
    for (int i = 0; i < 4; ++i)
#pragma unroll
        for (int j = 0; j < 4; ++j) acc[i][j] = 0ull;

    for (int k0 = 0; k0 < 256; k0 += 32) {
#pragma unroll
        for (int r = 0; r < 4; ++r) {
            int idx = tid + r * 256;
            int m = idx >> 3, q = idx & 7;
            int row = mBase + m;
            float4 v = make_float4(0.f, 0.f, 0.f, 0.f);
            if (row < total)
                v = *reinterpret_cast<const float4*>(&A[(size_t)row * 256 + k0 + q * 4]);
            As[q * 4 + 0][m] = v.x;
            As[q * 4 + 1][m] = v.y;
            As[q * 4 + 2][m] = v.z;
            As[q * 4 + 3][m] = v.w;
        }
#pragma unroll
        for (int r = 0; r < 2; ++r) {
            int idx = tid + r * 256;
            int n = idx >> 3, q = idx & 7;
            float4 v = *reinterpret_cast<const float4*>(&W[(size_t)(nBase + n) * 256 + k0 + q * 4]);
            Bs[q * 4 + 0][n] = v.x;
            Bs[q * 4 + 1][n] = v.y;
            Bs[q * 4 + 2][n] = v.z;
            Bs[q * 4 + 3][n] = v.w;
        }
        __syncthreads();

#pragma unroll
        for (int k = 0; k < 32; ++k) {
            ulonglong2 a01 = *reinterpret_cast<const ulonglong2*>(&As[k][ty * 8]);
            ulonglong2 a23 = *reinterpret_cast<const ulonglong2*>(&As[k][ty * 8 + 4]);
            float4 bv = *reinterpret_cast<const float4*>(&Bs[k][tx * 4]);
            ull bd0 = packf2(bv.x, bv.x);
            ull bd1 = packf2(bv.y, bv.y);
            ull bd2 = packf2(bv.z, bv.z);
            ull bd3 = packf2(bv.w, bv.w);
            acc[0][0] = ffma2(a01.x, bd0, acc[0][0]);
            acc[0][1] = ffma2(a01.x, bd1, acc[0][1]);
            acc[0][2] = ffma2(a01.x, bd2, acc[0][2]);
            acc[0][3] = ffma2(a01.x, bd3, acc[0][3]);
            acc[1][0] = ffma2(a01.y, bd0, acc[1][0]);
            acc[1][1] = ffma2(a01.y, bd1, acc[1][1]);
            acc[1][2] = ffma2(a01.y, bd2, acc[1][2]);
            acc[1][3] = ffma2(a01.y, bd3, acc[1][3]);
            acc[2][0] = ffma2(a23.x, bd0, acc[2][0]);
            acc[2][1] = ffma2(a23.x, bd1, acc[2][1]);
            acc[2][2] = ffma2(a23.x, bd2, acc[2][2]);
            acc[2][3] = ffma2(a23.x, bd3, acc[2][3]);
            acc[3][0] = ffma2(a23.y, bd0, acc[3][0]);
            acc[3][1] = ffma2(a23.y, bd1, acc[3][1]);
            acc[3][2] = ffma2(a23.y, bd2, acc[3][2]);
            acc[3][3] = ffma2(a23.y, bd3, acc[3][3]);
        }
        __syncthreads();
    }

#pragma unroll
    for (int i = 0; i < 4; ++i) {
        int tok0 = mBase + ty * 8 + 2 * i;
        int tok1 = tok0 + 1;
#pragma unroll
        for (int j = 0; j < 4; ++j) {
            float2 f = unpackf2(acc[i][j]);
            int gg   = nBase + tx * 4 + j;
            int dirr = gg >> 9;
            int g    = gg & 511;
            float bias = bi[gg] + bh[gg];
            if (tok0 < total)
                g_gpre[((size_t)dirr * total + tok0) * 512 + g] = f.x + bias;
            if (tok1 < total)
                g_gpre[((size_t)dirr * total + tok1) * 512 + g] = f.y + bias;
        }
    }
}

// ------------------------------------------------------------- recurrence ---
__device__ __forceinline__ float sigf(float x)
{
    return __fdividef(1.0f, 1.0f + __expf(-x));
}
__device__ __forceinline__ float tanhfast(float x)
{
    x = fminf(fmaxf(x, -12.0f), 12.0f);
    float e = __expf(2.0f * x);
    return __fdividef(e - 1.0f, e + 1.0f);
}

// 128 CTAs: blockIdx.x = dir*64 + b. 256 threads, 2 gates/thread (tid, tid+256).
// W_hh: k<64 -> fp32 f32x2 register pairs; k>=64 -> fp16 SMEM + HFMA2 (fp16 acc,
// 2 chains/gate). h kept as fp32 (k<64) and fp16 (k>=64) SMEM copies.
__global__ __launch_bounds__(256, 1)
void rec_kernel(const float* __restrict__ Whh_all,
                const float* __restrict__ h0,
                const float* __restrict__ c0,
                float* __restrict__ dout,
                int total, int T, int layer)
{
    extern __shared__ char smem[];
    __half* wh  = reinterpret_cast<__half*>(smem);                 // [8 chunks][512 g][8 half] = 64KB
    float*  hs  = reinterpret_cast<float*>(smem + 65536);          // 128 f32
    __half* hsh = reinterpret_cast<__half*>(smem + 65536 + 512);   // 64 fp16 (h[64..127])
    float*  zs  = reinterpret_cast<float*>(smem + 65536 + 512 + 128); // 512 f32
    int*    offs = reinterpret_cast<int*>(smem + 65536 + 512 + 128 + 2048);

    const int tid = threadIdx.x;
    const int dir = blockIdx.x >> 6;
    const int b   = blockIdx.x & 63;
    const int kix = 2 * layer + dir;

    const float* gpd = g_gpre + (size_t)dir * (size_t)total * 512;
    const float* W   = Whh_all + (size_t)kix * 512 * 128;
    float* outb = (layer == 0) ? g_out1 : dout;

    for (int i = tid; i < T; i += 256) offs[i] = g_offsets[i];

    // fp16 half of W: k in [64,128), chunk c = (k-64)/8, 8 halves per (c,g)
    for (int i = tid; i < 512 * 8; i += 256) {
        int c = i >> 9, g = i & 511;
        const float* ws = &W[g * 128 + 64 + c * 8];
        float4 w0 = *reinterpret_cast<const float4*>(ws);
        float4 w1 = *reinterpret_cast<const float4*>(ws + 4);
        __half2 p0 = __floats2half2_rn(w0.x, w0.y);
        __half2 p1 = __floats2half2_rn(w0.z, w0.w);
        __half2 p2 = __floats2half2_rn(w1.x, w1.y);
        __half2 p3 = __floats2half2_rn(w1.z, w1.w);
        uint4 u;
        u.x = *reinterpret_cast<unsigned int*>(&p0);
        u.y = *reinterpret_cast<unsigned int*>(&p1);
        u.z = *reinterpret_cast<unsigned int*>(&p2);
        u.w = *reinterpret_cast<unsigned int*>(&p3);
        *reinterpret_cast<uint4*>(&wh[(c * 512 + g) * 8]) = u;
    }

    // fp32 register half of W: k<64 for gates g0=tid, g1=tid+256
    ull wr[2][32];
#pragma unroll
    for (int e = 0; e < 2; ++e) {
        const float* wg = &W[(tid + 256 * e) * 128];
#pragma unroll
        for (int p = 0; p < 32; ++p) {
            float2 wv = *reinterpret_cast<const float2*>(&wg[2 * p]);
            wr[e][p] = packf2(wv.x, wv.y);
        }
    }

    float creg = 0.f;
    if (tid < 128) {
        float hv = h0[(size_t)kix * 8192 + b * 128 + tid];
        hs[tid] = hv;
        if (tid >= 64) hsh[tid - 64] = __float2half_rn(hv);
        creg = c0[(size_t)kix * 8192 + b * 128 + tid];
    }
    __syncthreads();

    const int  len = g_len[b];
    const bool fwd = (dir == 0);

    int   tok = offs[fwd ? 0 : (len - 1)] + b;
    float gcur0 = gpd[(size_t)tok * 512 + tid];
    float gcur1 = gpd[(size_t)tok * 512 + tid + 256];

    const double2* h2p = reinterpret_cast<const double2*>(hs);
    const uint4*   hhp = reinterpret_cast<const uint4*>(hsh);
    const uint4*   whp = reinterpret_cast<const uint4*>(wh);
    const __half2  hzero = __floats2half2_rn(0.f, 0.f);

    for (int s = 0; s < len; ++s) {
        int   toknext = 0;
        float gnext0 = 0.f, gnext1 = 0.f;
        if (s + 1 < len) {
            int tn  = fwd ? (s + 1) : (len - 2 - s);
            toknext = offs[tn] + b;
            gnext0  = gpd[(size_t)toknext * 512 + tid];
            gnext1  = gpd[(size_t)toknext * 512 + tid + 256];
        }

        float z[2];
#pragma unroll
        for (int e = 0; e < 2; ++e) {
            ull a0 = 0ull, a1 = 0ull;
#pragma unroll
            for (int q = 0; q < 16; ++q) {
                double2 h2 = h2p[q];
                a0 = ffma2(wr[e][2 * q],     __double_as_longlong(h2.x), a0);
                a1 = ffma2(wr[e][2 * q + 1], __double_as_longlong(h2.y), a1);
            }
            __half2 hc0 = hzero, hc1 = hzero;
            const uint4* wgp = whp + (tid + 256 * e);
#pragma unroll
            for (int c = 0; c < 8; ++c) {
                uint4 wv = wgp[c * 512];
                uint4 hv = hhp[c];
                hc0 = __hfma2(uh2(wv.x), uh2(hv.x), hc0);
                hc1 = __hfma2(uh2(wv.y), uh2(hv.y), hc1);
                hc0 = __hfma2(uh2(wv.z), uh2(hv.z), hc0);
                hc1 = __hfma2(uh2(wv.w), uh2(hv.w), hc1);
            }
            float2 fa = unpackf2(a0);
            float2 fb = unpackf2(a1);
            float2 f0 = __half22float2(hc0);
            float2 f1 = __half22float2(hc1);
            z[e] = ((e == 0) ? gcur0 : gcur1)
                 + (fa.x + fa.y) + (fb.x + fb.y)
                 + (f0.x + f0.y) + (f1.x + f1.y);
        }
        zs[tid]       = z[0];
        zs[tid + 256] = z[1];
        __syncthreads();

        if (tid < 128) {
            float zi = zs[tid];
            float zf = zs[tid + 128];
            float zg = zs[tid + 256];
            float zo = zs[tid + 384];
            float ig = sigf(zi);
            float fg = sigf(zf);
            float gv = tanhfast(zg);
            float og = sigf(zo);
            creg = fg * creg + ig * gv;
            float hv = og * tanhfast(creg);
            hs[tid] = hv;
            if (tid >= 64) hsh[tid - 64] = __float2half_rn(hv);
            outb[(size_t)tok * 256 + dir * 128 + tid] = hv;
        }
        __syncthreads();

        gcur0 = gnext0;
        gcur1 = gnext1;
        tok   = toknext;
    }

    if (tid < 128) {
        float* hn = dout + (size_t)total * 256 + (size_t)kix * 8192 + (size_t)b * 128;
        float* cn = hn + 4 * 64 * 128;
        hn[tid] = hs[tid];
        cn[tid] = creg;
    }
}

// ---------------------------------------------------------------- launch ----
extern "C" void kernel_launch(void* const* d_in, const int* in_sizes, int n_in,
                              void* d_out, int out_size)
{
    const float* input       = (const float*)d_in[0];
    const int*   batch_sizes = (const int*)  d_in[1];
    const float* h0          = (const float*)d_in[2];
    const float* c0          = (const float*)d_in[3];
    const float* W_ih        = (const float*)d_in[4];
    const float* W_hh        = (const float*)d_in[5];
    const float* b_ih        = (const float*)d_in[6];
    const float* b_hh        = (const float*)d_in[7];
    float* out = (float*)d_out;

    int T     = in_sizes[1];
    int total = in_sizes[0] / 256;
    if (total > TOTAL_MAX) total = TOTAL_MAX;
    if (T > TMAX) T = TMAX;

    const int REC_SMEM = 65536 + 512 + 128 + 2048 + TMAX * 4;  // 72320 B
    cudaFuncSetAttribute(rec_kernel, cudaFuncAttributeMaxDynamicSharedMemorySize, REC_SMEM);

    setup_kernel<<<1, 1024>>>(batch_sizes, T);

    dim3 ggrid((total + 127) / 128, 16);
    // layer 0
    gemm_kernel<<<ggrid, 256>>>(input, W_ih, b_ih, b_hh, total, 0);
    rec_kernel<<<128, 256, REC_SMEM>>>(W_hh, h0, c0, out, total, T, 0);
    // layer 1
    gemm_kernel<<<ggrid, 256>>>(input, W_ih, b_ih, b_hh, total, 1);
    rec_kernel<<<128, 256, REC_SMEM>>>(W_hh, h0, c0, out, total, T, 1);
}

// round 6
// speedup vs baseline: 2.1770x; 1.5226x over previous
#include <cuda_runtime.h>
#include <cuda_fp16.h>
#include <cstdint>

// ----------------------------------------------------------------------------
// Packed bidirectional 2-layer LSTM.
//   inputs : input(total,256) f32, batch_sizes(T) i32, h0(4,64,128), c0(4,64,128),
//            W_ih(4,512,256), W_hh(4,512,128), b_ih(4,512), b_hh(4,512)
//   outputs: packed_out(total,256) | h_n(4,64,128) | c_n(4,64,128)
// ----------------------------------------------------------------------------

#define TOTAL_MAX 49408
#define TMAX      1024
#define AK        72            // padded smem stride in halves (144B, conflict-free)

__device__ float  g_gpre[2 * TOTAL_MAX * 512];
__device__ __half g_A16 [TOTAL_MAX * 256];      // layer-0 input, fp16
__device__ __half g_out1h[TOTAL_MAX * 256];     // layer-1 input (rec-l0 output), fp16
__device__ __half g_W16 [4 * 512 * 256];        // W_ih in fp16
__device__ int    g_offsets[TMAX];
__device__ int    g_len[64];

typedef unsigned long long ull;

__device__ __forceinline__ ull ffma2(ull a, ull b, ull c)
{
    ull d;
    asm("fma.rn.f32x2 %0, %1, %2, %3;" : "=l"(d) : "l"(a), "l"(b), "l"(c));
    return d;
}
__device__ __forceinline__ ull packf2(float lo, float hi)
{
    ull r;
    asm("mov.b64 %0, {%1, %2};" : "=l"(r) : "f"(lo), "f"(hi));
    return r;
}
__device__ __forceinline__ float2 unpackf2(ull v)
{
    float2 f;
    asm("mov.b64 {%0, %1}, %2;" : "=f"(f.x), "=f"(f.y) : "l"(v));
    return f;
}
__device__ __forceinline__ __half2 uh2(unsigned int u)
{
    return *reinterpret_cast<__half2*>(&u);
}

// ---- HMMA building blocks (scalar-ref asm operands, example-proven style) ----
__device__ __forceinline__ void cp16(uint32_t saddr, const void* gptr)
{
    asm volatile("cp.async.cg.shared.global [%0], [%1], 16;"
                 :: "r"(saddr), "l"(gptr) : "memory");
}
__device__ __forceinline__ void ldsm_x4(uint32_t& r0, uint32_t& r1,
                                        uint32_t& r2, uint32_t& r3, uint32_t addr)
{
    asm volatile("ldmatrix.sync.aligned.m8n8.x4.shared.b16 {%0,%1,%2,%3}, [%4];"
                 : "=r"(r0), "=r"(r1), "=r"(r2), "=r"(r3) : "r"(addr));
}
__device__ __forceinline__ void ldsm_x2(uint32_t& r0, uint32_t& r1, uint32_t addr)
{
    asm volatile("ldmatrix.sync.aligned.m8n8.x2.shared.b16 {%0,%1}, [%2];"
                 : "=r"(r0), "=r"(r1) : "r"(addr));
}
__device__ __forceinline__ void mma16816(float* c,
                                         uint32_t a0, uint32_t a1, uint32_t a2, uint32_t a3,
                                         uint32_t b0, uint32_t b1)
{
    asm volatile("mma.sync.aligned.m16n8k16.row.col.f32.f16.f16.f32 "
                 "{%0,%1,%2,%3}, {%4,%5,%6,%7}, {%8,%9}, {%0,%1,%2,%3};"
                 : "+f"(c[0]), "+f"(c[1]), "+f"(c[2]), "+f"(c[3])
                 : "r"(a0), "r"(a1), "r"(a2), "r"(a3), "r"(b0), "r"(b1));
}

// ---------------------------------------------------------------- setup -----
__global__ void setup_kernel(const int* __restrict__ bs, int T)
{
    __shared__ int s[TMAX];
    int tid = threadIdx.x;
    if (tid < T) s[tid] = bs[tid];
    __syncthreads();
    if (tid == 0) {
        int off = 0;
        for (int t = 0; t < T; ++t) { g_offsets[t] = off; off += s[t]; }
    }
    if (tid < 64) {
        int c = 0;
        for (int t = 0; t < T; ++t) c += (s[t] > tid) ? 1 : 0;
        g_len[tid] = c;
    }
}

// f32 -> f16 bulk convert (float4 granularity)
__global__ void cvt_kernel(const float* __restrict__ src, __half* __restrict__ dst, int n4)
{
    int i = blockIdx.x * blockDim.x + threadIdx.x;
    if (i < n4) {
        float4 v = reinterpret_cast<const float4*>(src)[i];
        __half2 lo = __floats2half2_rn(v.x, v.y);
        __half2 hi = __floats2half2_rn(v.z, v.w);
        uint2 u;
        u.x = *reinterpret_cast<unsigned int*>(&lo);
        u.y = *reinterpret_cast<unsigned int*>(&hi);
        reinterpret_cast<uint2*>(dst)[i] = u;
    }
}

// ------------------------------------------------------------ HMMA gemm -----
// gpre[dir][tok][g] = A16[tok][:] . W16[layer][dir*512+g][:] + bias
// CTA tile 128(m) x 128(n). K=256 in 4 stages of 64, double-buffered cp.async.
// 8 warps: warpM(2) x warpN(4); warp tile 64x32; mma.m16n8k16 f16 -> f32.
__global__ __launch_bounds__(256, 1)
void gemm_hmma(const __half* __restrict__ Ah,
               const float* __restrict__ bih_all,
               const float* __restrict__ bhh_all,
               int total, int layer)
{
    extern __shared__ __half shbuf[];
    const int STAGE = 2 * 128 * AK;                 // halves per stage (A + B tiles)
    const uint32_t sbase = (uint32_t)__cvta_generic_to_shared(shbuf);

    const __half* Wl = g_W16 + (size_t)layer * 262144;
    const float*  bi = bih_all + layer * 1024;
    const float*  bh = bhh_all + layer * 1024;

    const int tid   = threadIdx.x;
    const int lane  = tid & 31;
    const int wid   = tid >> 5;
    const int warpM = wid >> 2;                     // 0..1
    const int warpN = wid & 3;                      // 0..3
    const int mBase = blockIdx.x * 128;
    const int nBase = blockIdx.y * 128;

    const int r0 = tid >> 3;                        // cp.async row (0..31)
    const int c0 = tid & 7;                         // 16B chunk (0..7)

    const int grp  = lane >> 3;
    const int rinl = lane & 7;
    const int aRow = warpM * 64 + (grp & 1) * 8 + rinl;
    const int aCol = (grp >> 1) * 8;
    const int bRowBase = warpN * 32 + rinl;
    const int bCol = ((lane >> 3) & 1) * 8;

    float acc[4][4][4];
#pragma unroll
    for (int i = 0; i < 4; ++i)
#pragma unroll
        for (int j = 0; j < 4; ++j)
#pragma unroll
            for (int v = 0; v < 4; ++v) acc[i][j][v] = 0.f;

    // ---- prologue: stage 0 into buffer 0
#pragma unroll
    for (int i = 0; i < 4; ++i) {
        int r = r0 + i * 32;
        int arow = mBase + r;
        if (arow > total - 1) arow = total - 1;
        cp16(sbase + (uint32_t)(r * AK + c0 * 8) * 2,
             Ah + (size_t)arow * 256 + c0 * 8);
        cp16(sbase + (uint32_t)(128 * AK + r * AK + c0 * 8) * 2,
             Wl + (size_t)(nBase + r) * 256 + c0 * 8);
    }
    asm volatile("cp.async.commit_group;" ::: "memory");

    for (int s = 0; s < 4; ++s) {
        if (s < 3) {
            const int ks  = s + 1;
            const int nbf = ks & 1;
#pragma unroll
            for (int i = 0; i < 4; ++i) {
                int r = r0 + i * 32;
                int arow = mBase + r;
                if (arow > total - 1) arow = total - 1;
                cp16(sbase + (uint32_t)(nbf * STAGE + r * AK + c0 * 8) * 2,
                     Ah + (size_t)arow * 256 + ks * 64 + c0 * 8);
                cp16(sbase + (uint32_t)(nbf * STAGE + 128 * AK + r * AK + c0 * 8) * 2,
                     Wl + (size_t)(nBase + r) * 256 + ks * 64 + c0 * 8);
            }
        }
        asm volatile("cp.async.commit_group;" ::: "memory");
        if (s < 3) asm volatile("cp.async.wait_group 1;" ::: "memory");
        else       asm volatile("cp.async.wait_group 0;" ::: "memory");
        __syncthreads();

        const int buf = s & 1;
        const uint32_t aTile = sbase + (uint32_t)(buf * STAGE) * 2;
        const uint32_t bTile = sbase + (uint32_t)(buf * STAGE + 128 * AK) * 2;

#pragma unroll
        for (int kk = 0; kk < 4; ++kk) {
            uint32_t af[4][4];
            uint32_t bf[4][2];
#pragma unroll
            for (int mf = 0; mf < 4; ++mf) {
                uint32_t aaddr = aTile +
                    (uint32_t)((aRow + mf * 16) * AK + kk * 16 + aCol) * 2;
                ldsm_x4(af[mf][0], af[mf][1], af[mf][2], af[mf][3], aaddr);
            }
#pragma unroll
            for (int nf = 0; nf < 4; ++nf) {
                uint32_t baddr = bTile +
                    (uint32_t)((bRowBase + nf * 8) * AK + kk * 16 + bCol) * 2;
                ldsm_x2(bf[nf][0], bf[nf][1], baddr);
            }
#pragma unroll
            for (int mf = 0; mf < 4; ++mf)
#pragma unroll
                for (int nf = 0; nf < 4; ++nf)
                    mma16816(acc[mf][nf],
                             af[mf][0], af[mf][1], af[mf][2], af[mf][3],
                             bf[nf][0], bf[nf][1]);
        }
        __syncthreads();
    }

    // ---- epilogue: bias add + scatter to g_gpre[dir][tok][g]
    const int mW = mBase + warpM * 64 + (lane >> 2);
    const int nW = nBase + warpN * 32 + ((lane & 3) << 1);
#pragma unroll
    for (int nf = 0; nf < 4; ++nf) {
        int n = nW + nf * 8;
        float bias0 = bi[n] + bh[n];
        float bias1 = bi[n + 1] + bh[n + 1];
        int dirr = n >> 9;
        int g    = n & 511;
        float* gp = g_gpre + (size_t)dirr * (size_t)total * 512 + g;
#pragma unroll
        for (int mf = 0; mf < 4; ++mf) {
            int m0 = mW + mf * 16;
            if (m0 < total) {
                float2 v = make_float2(acc[mf][nf][0] + bias0, acc[mf][nf][1] + bias1);
                *reinterpret_cast<float2*>(gp + (size_t)m0 * 512) = v;
            }
            int m1 = m0 + 8;
            if (m1 < total) {
                float2 v = make_float2(acc[mf][nf][2] + bias0, acc[mf][nf][3] + bias1);
                *reinterpret_cast<float2*>(gp + (size_t)m1 * 512) = v;
            }
        }
    }
}

// ------------------------------------------------------------- recurrence ---
__device__ __forceinline__ float sigf(float x)
{
    return __fdividef(1.0f, 1.0f + __expf(-x));
}
__device__ __forceinline__ float tanhfast(float x)
{
    x = fminf(fmaxf(x, -12.0f), 12.0f);
    float e = __expf(2.0f * x);
    return __fdividef(e - 1.0f, e + 1.0f);
}

// 128 CTAs: blockIdx.x = dir*64 + b. 256 threads, 2 gates/thread (tid, tid+256).
// W_hh: k<64 -> fp32 f32x2 register pairs; k>=64 -> fp16 SMEM + HFMA2.
__global__ __launch_bounds__(256, 1)
void rec_kernel(const float* __restrict__ Whh_all,
                const float* __restrict__ h0,
                const float* __restrict__ c0,
                float* __restrict__ dout,
                int total, int T, int layer)
{
    extern __shared__ char smem[];
    __half* wh  = reinterpret_cast<__half*>(smem);                 // 64KB
    float*  hs  = reinterpret_cast<float*>(smem + 65536);          // 128 f32
    __half* hsh = reinterpret_cast<__half*>(smem + 65536 + 512);   // 64 fp16
    float*  zs  = reinterpret_cast<float*>(smem + 65536 + 512 + 128);
    int*    offs = reinterpret_cast<int*>(smem + 65536 + 512 + 128 + 2048);

    const int tid = threadIdx.x;
    const int dir = blockIdx.x >> 6;
    const int b   = blockIdx.x & 63;
    const int kix = 2 * layer + dir;

    const float* gpd = g_gpre + (size_t)dir * (size_t)total * 512;
    const float* W   = Whh_all + (size_t)kix * 512 * 128;

    for (int i = tid; i < T; i += 256) offs[i] = g_offsets[i];

    for (int i = tid; i < 512 * 8; i += 256) {
        int c = i >> 9, g = i & 511;
        const float* ws = &W[g * 128 + 64 + c * 8];
        float4 w0 = *reinterpret_cast<const float4*>(ws);
        float4 w1 = *reinterpret_cast<const float4*>(ws + 4);
        __half2 p0 = __floats2half2_rn(w0.x, w0.y);
        __half2 p1 = __floats2half2_rn(w0.z, w0.w);
        __half2 p2 = __floats2half2_rn(w1.x, w1.y);
        __half2 p3 = __floats2half2_rn(w1.z, w1.w);
        uint4 u;
        u.x = *reinterpret_cast<unsigned int*>(&p0);
        u.y = *reinterpret_cast<unsigned int*>(&p1);
        u.z = *reinterpret_cast<unsigned int*>(&p2);
        u.w = *reinterpret_cast<unsigned int*>(&p3);
        *reinterpret_cast<uint4*>(&wh[(c * 512 + g) * 8]) = u;
    }

    ull wr[2][32];
#pragma unroll
    for (int e = 0; e < 2; ++e) {
        const float* wg = &W[(tid + 256 * e) * 128];
#pragma unroll
        for (int p = 0; p < 32; ++p) {
            float2 wv = *reinterpret_cast<const float2*>(&wg[2 * p]);
            wr[e][p] = packf2(wv.x, wv.y);
        }
    }

    float creg = 0.f;
    if (tid < 128) {
        float hv = h0[(size_t)kix * 8192 + b * 128 + tid];
        hs[tid] = hv;
        if (tid >= 64) hsh[tid - 64] = __float2half_rn(hv);
        creg = c0[(size_t)kix * 8192 + b * 128 + tid];
    }
    __syncthreads();

    const int  len = g_len[b];
    const bool fwd = (dir == 0);

    int   tok = offs[fwd ? 0 : (len - 1)] + b;
    float gcur0 = gpd[(size_t)tok * 512 + tid];
    float gcur1 = gpd[(size_t)tok * 512 + tid + 256];

    const double2* h2p = reinterpret_cast<const double2*>(hs);
    const uint4*   hhp = reinterpret_cast<const uint4*>(hsh);
    const uint4*   whp = reinterpret_cast<const uint4*>(wh);
    const __half2  hzero = __floats2half2_rn(0.f, 0.f);

    for (int s = 0; s < len; ++s) {
        int   toknext = 0;
        float gnext0 = 0.f, gnext1 = 0.f;
        if (s + 1 < len) {
            int tn  = fwd ? (s + 1) : (len - 2 - s);
            toknext = offs[tn] + b;
            gnext0  = gpd[(size_t)toknext * 512 + tid];
            gnext1  = gpd[(size_t)toknext * 512 + tid + 256];
        }

        float z[2];
#pragma unroll
        for (int e = 0; e < 2; ++e) {
            ull a0 = 0ull, a1 = 0ull;
#pragma unroll
            for (int q = 0; q < 16; ++q) {
                double2 h2 = h2p[q];
                a0 = ffma2(wr[e][2 * q],     __double_as_longlong(h2.x), a0);
                a1 = ffma2(wr[e][2 * q + 1], __double_as_longlong(h2.y), a1);
            }
            __half2 hc0 = hzero, hc1 = hzero;
            const uint4* wgp = whp + (tid + 256 * e);
#pragma unroll
            for (int c = 0; c < 8; ++c) {
                uint4 wv = wgp[c * 512];
                uint4 hv = hhp[c];
                hc0 = __hfma2(uh2(wv.x), uh2(hv.x), hc0);
                hc1 = __hfma2(uh2(wv.y), uh2(hv.y), hc1);
                hc0 = __hfma2(uh2(wv.z), uh2(hv.z), hc0);
                hc1 = __hfma2(uh2(wv.w), uh2(hv.w), hc1);
            }
            float2 fa = unpackf2(a0);
            float2 fb = unpackf2(a1);
            float2 f0 = __half22float2(hc0);
            float2 f1 = __half22float2(hc1);
            z[e] = ((e == 0) ? gcur0 : gcur1)
                 + (fa.x + fa.y) + (fb.x + fb.y)
                 + (f0.x + f0.y) + (f1.x + f1.y);
        }
        zs[tid]       = z[0];
        zs[tid + 256] = z[1];
        __syncthreads();

        if (tid < 128) {
            float zi = zs[tid];
            float zf = zs[tid + 128];
            float zg = zs[tid + 256];
            float zo = zs[tid + 384];
            float ig = sigf(zi);
            float fg = sigf(zf);
            float gv = tanhfast(zg);
            float og = sigf(zo);
            creg = fg * creg + ig * gv;
            float hv = og * tanhfast(creg);
            hs[tid] = hv;
            if (tid >= 64) hsh[tid - 64] = __float2half_rn(hv);
            if (layer == 0)
                g_out1h[(size_t)tok * 256 + dir * 128 + tid] = __float2half_rn(hv);
            else
                dout[(size_t)tok * 256 + dir * 128 + tid] = hv;
        }
        __syncthreads();

        gcur0 = gnext0;
        gcur1 = gnext1;
        tok   = toknext;
    }

    if (tid < 128) {
        float* hn = dout + (size_t)total * 256 + (size_t)kix * 8192 + (size_t)b * 128;
        float* cn = hn + 4 * 64 * 128;
        hn[tid] = hs[tid];
        cn[tid] = creg;
    }
}

// ---------------------------------------------------------------- launch ----
extern "C" void kernel_launch(void* const* d_in, const int* in_sizes, int n_in,
                              void* d_out, int out_size)
{
    const float* input       = (const float*)d_in[0];
    const int*   batch_sizes = (const int*)  d_in[1];
    const float* h0          = (const float*)d_in[2];
    const float* c0          = (const float*)d_in[3];
    const float* W_ih        = (const float*)d_in[4];
    const float* W_hh        = (const float*)d_in[5];
    const float* b_ih        = (const float*)d_in[6];
    const float* b_hh        = (const float*)d_in[7];
    float* out = (float*)d_out;

    int T     = in_sizes[1];
    int total = in_sizes[0] / 256;
    if (total > TOTAL_MAX) total = TOTAL_MAX;
    if (T > TMAX) T = TMAX;

    const int REC_SMEM  = 65536 + 512 + 128 + 2048 + TMAX * 4;   // 72320 B
    const int GEMM_SMEM = 2 * (2 * 128 * AK) * 2;                // 73728 B
    cudaFuncSetAttribute(rec_kernel, cudaFuncAttributeMaxDynamicSharedMemorySize, REC_SMEM);
    cudaFuncSetAttribute(gemm_hmma, cudaFuncAttributeMaxDynamicSharedMemorySize, GEMM_SMEM);

    setup_kernel<<<1, 1024>>>(batch_sizes, T);

    // fp16 prepass: layer-0 A and all W_ih
    __half* dA16;   cudaGetSymbolAddress((void**)&dA16, g_A16);
    __half* dW16;   cudaGetSymbolAddress((void**)&dW16, g_W16);
    __half* dOut1h; cudaGetSymbolAddress((void**)&dOut1h, g_out1h);
    {
        int n4a = in_sizes[0] / 4;
        int n4w = in_sizes[4] / 4;
        cvt_kernel<<<(n4a + 255) / 256, 256>>>(input, dA16, n4a);
        cvt_kernel<<<(n4w + 255) / 256, 256>>>(W_ih, dW16, n4w);
    }

    dim3 ggrid((total + 127) / 128, 8);
    // layer 0
    gemm_hmma<<<ggrid, 256, GEMM_SMEM>>>(dA16, b_ih, b_hh, total, 0);
    rec_kernel<<<128, 256, REC_SMEM>>>(W_hh, h0, c0, out, total, T, 0);
    // layer 1
    gemm_hmma<<<ggrid, 256, GEMM_SMEM>>>(dOut1h, b_ih, b_hh, total, 1);
    rec_kernel<<<128, 256, REC_SMEM>>>(W_hh, h0, c0, out, total, T, 1);
}

// round 7
// speedup vs baseline: 2.6056x; 1.1969x over previous
#include <cuda_runtime.h>
#include <cuda_fp16.h>
#include <cstdint>

// ----------------------------------------------------------------------------
// Packed bidirectional 2-layer LSTM.
//   inputs : input(total,256) f32, batch_sizes(T) i32, h0(4,64,128), c0(4,64,128),
//            W_ih(4,512,256), W_hh(4,512,128), b_ih(4,512), b_hh(4,512)
//   outputs: packed_out(total,256) | h_n(4,64,128) | c_n(4,64,128)
// ----------------------------------------------------------------------------

#define TOTAL_MAX 49408
#define TMAX      1024
#define AK        72            // padded smem stride in halves (144B, conflict-free)

__device__ float  g_gpre[2 * TOTAL_MAX * 512];
__device__ __half g_A16 [TOTAL_MAX * 256];      // layer-0 input, fp16
__device__ __half g_out1h[TOTAL_MAX * 256];     // layer-1 input (rec-l0 output), fp16
__device__ __half g_W16 [4 * 512 * 256];        // W_ih in fp16
__device__ int    g_offsets[TMAX];
__device__ int    g_len[64];

typedef unsigned long long ull;

__device__ __forceinline__ ull ffma2(ull a, ull b, ull c)
{
    ull d;
    asm("fma.rn.f32x2 %0, %1, %2, %3;" : "=l"(d) : "l"(a), "l"(b), "l"(c));
    return d;
}
__device__ __forceinline__ ull packf2(float lo, float hi)
{
    ull r;
    asm("mov.b64 %0, {%1, %2};" : "=l"(r) : "f"(lo), "f"(hi));
    return r;
}
__device__ __forceinline__ float2 unpackf2(ull v)
{
    float2 f;
    asm("mov.b64 {%0, %1}, %2;" : "=f"(f.x), "=f"(f.y) : "l"(v));
    return f;
}
__device__ __forceinline__ __half2 uh2(unsigned int u)
{
    return *reinterpret_cast<__half2*>(&u);
}
__device__ __forceinline__ unsigned int h2u(__half2 h)
{
    return *reinterpret_cast<unsigned int*>(&h);
}

// ---- HMMA building blocks ----
__device__ __forceinline__ void cp16(uint32_t saddr, const void* gptr)
{
    asm volatile("cp.async.cg.shared.global [%0], [%1], 16;"
                 :: "r"(saddr), "l"(gptr) : "memory");
}
__device__ __forceinline__ void ldsm_x4(uint32_t& r0, uint32_t& r1,
                                        uint32_t& r2, uint32_t& r3, uint32_t addr)
{
    asm volatile("ldmatrix.sync.aligned.m8n8.x4.shared.b16 {%0,%1,%2,%3}, [%4];"
                 : "=r"(r0), "=r"(r1), "=r"(r2), "=r"(r3) : "r"(addr));
}
__device__ __forceinline__ void ldsm_x2(uint32_t& r0, uint32_t& r1, uint32_t addr)
{
    asm volatile("ldmatrix.sync.aligned.m8n8.x2.shared.b16 {%0,%1}, [%2];"
                 : "=r"(r0), "=r"(r1) : "r"(addr));
}
__device__ __forceinline__ void mma16816(float* c,
                                         uint32_t a0, uint32_t a1, uint32_t a2, uint32_t a3,
                                         uint32_t b0, uint32_t b1)
{
    asm volatile("mma.sync.aligned.m16n8k16.row.col.f32.f16.f16.f32 "
                 "{%0,%1,%2,%3}, {%4,%5,%6,%7}, {%8,%9}, {%0,%1,%2,%3};"
                 : "+f"(c[0]), "+f"(c[1]), "+f"(c[2]), "+f"(c[3])
                 : "r"(a0), "r"(a1), "r"(a2), "r"(a3), "r"(b0), "r"(b1));
}

// ---------------------------------------------------------------- setup -----
__global__ void setup_kernel(const int* __restrict__ bs, int T)
{
    __shared__ int s[TMAX];
    int tid = threadIdx.x;
    if (tid < T) s[tid] = bs[tid];
    __syncthreads();
    if (tid == 0) {
        int off = 0;
        for (int t = 0; t < T; ++t) { g_offsets[t] = off; off += s[t]; }
    }
    if (tid < 64) {
        int c = 0;
        for (int t = 0; t < T; ++t) c += (s[t] > tid) ? 1 : 0;
        g_len[tid] = c;
    }
}

// f32 -> f16 bulk convert (float4 granularity)
__global__ void cvt_kernel(const float* __restrict__ src, __half* __restrict__ dst, int n4)
{
    int i = blockIdx.x * blockDim.x + threadIdx.x;
    if (i < n4) {
        float4 v = reinterpret_cast<const float4*>(src)[i];
        __half2 lo = __floats2half2_rn(v.x, v.y);
        __half2 hi = __floats2half2_rn(v.z, v.w);
        uint2 u;
        u.x = h2u(lo);
        u.y = h2u(hi);
        reinterpret_cast<uint2*>(dst)[i] = u;
    }
}

// ------------------------------------------------------------ HMMA gemm -----
// gpre[dir][tok][g] = A16[tok][:] . W16[layer][dir*512+g][:] + bias
// CTA tile 128(m) x 128(n). K=256 in 4 stages of 64, double-buffered cp.async.
// 8 warps: warpM(2) x warpN(4); warp tile 64x32; mma.m16n8k16 f16 -> f32.
__global__ __launch_bounds__(256, 2)
void gemm_hmma(const __half* __restrict__ Ah,
               const float* __restrict__ bih_all,
               const float* __restrict__ bhh_all,
               int total, int layer)
{
    extern __shared__ __half shbuf[];
    const int STAGE = 2 * 128 * AK;                 // halves per stage (A + B tiles)
    const uint32_t sbase = (uint32_t)__cvta_generic_to_shared(shbuf);

    const __half* Wl = g_W16 + (size_t)layer * 262144;
    const float*  bi = bih_all + layer * 1024;
    const float*  bh = bhh_all + layer * 1024;

    const int tid   = threadIdx.x;
    const int lane  = tid & 31;
    const int wid   = tid >> 5;
    const int warpM = wid >> 2;                     // 0..1
    const int warpN = wid & 3;                      // 0..3
    const int mBase = blockIdx.x * 128;
    const int nBase = blockIdx.y * 128;

    const int r0 = tid >> 3;                        // cp.async row (0..31)
    const int c0 = tid & 7;                         // 16B chunk (0..7)

    const int grp  = lane >> 3;
    const int rinl = lane & 7;
    const int aRow = warpM * 64 + (grp & 1) * 8 + rinl;
    const int aCol = (grp >> 1) * 8;
    const int bRowBase = warpN * 32 + rinl;
    const int bCol = ((lane >> 3) & 1) * 8;

    float acc[4][4][4];
#pragma unroll
    for (int i = 0; i < 4; ++i)
#pragma unroll
        for (int j = 0; j < 4; ++j)
#pragma unroll
            for (int v = 0; v < 4; ++v) acc[i][j][v] = 0.f;

    // ---- prologue: stage 0 into buffer 0
#pragma unroll
    for (int i = 0; i < 4; ++i) {
        int r = r0 + i * 32;
        int arow = mBase + r;
        if (arow > total - 1) arow = total - 1;
        cp16(sbase + (uint32_t)(r * AK + c0 * 8) * 2,
             Ah + (size_t)arow * 256 + c0 * 8);
        cp16(sbase + (uint32_t)(128 * AK + r * AK + c0 * 8) * 2,
             Wl + (size_t)(nBase + r) * 256 + c0 * 8);
    }
    asm volatile("cp.async.commit_group;" ::: "memory");

    for (int s = 0; s < 4; ++s) {
        if (s < 3) {
            const int ks  = s + 1;
            const int nbf = ks & 1;
#pragma unroll
            for (int i = 0; i < 4; ++i) {
                int r = r0 + i * 32;
                int arow = mBase + r;
                if (arow > total - 1) arow = total - 1;
                cp16(sbase + (uint32_t)(nbf * STAGE + r * AK + c0 * 8) * 2,
                     Ah + (size_t)arow * 256 + ks * 64 + c0 * 8);
                cp16(sbase + (uint32_t)(nbf * STAGE + 128 * AK + r * AK + c0 * 8) * 2,
                     Wl + (size_t)(nBase + r) * 256 + ks * 64 + c0 * 8);
            }
        }
        asm volatile("cp.async.commit_group;" ::: "memory");
        if (s < 3) asm volatile("cp.async.wait_group 1;" ::: "memory");
        else       asm volatile("cp.async.wait_group 0;" ::: "memory");
        __syncthreads();

        const int buf = s & 1;
        const uint32_t aTile = sbase + (uint32_t)(buf * STAGE) * 2;
        const uint32_t bTile = sbase + (uint32_t)(buf * STAGE + 128 * AK) * 2;

#pragma unroll
        for (int kk = 0; kk < 4; ++kk) {
            uint32_t af[4][4];
            uint32_t bf[4][2];
#pragma unroll
            for (int mf = 0; mf < 4; ++mf) {
                uint32_t aaddr = aTile +
                    (uint32_t)((aRow + mf * 16) * AK + kk * 16 + aCol) * 2;
                ldsm_x4(af[mf][0], af[mf][1], af[mf][2], af[mf][3], aaddr);
            }
#pragma unroll
            for (int nf = 0; nf < 4; ++nf) {
                uint32_t baddr = bTile +
                    (uint32_t)((bRowBase + nf * 8) * AK + kk * 16 + bCol) * 2;
                ldsm_x2(bf[nf][0], bf[nf][1], baddr);
            }
#pragma unroll
            for (int mf = 0; mf < 4; ++mf)
#pragma unroll
                for (int nf = 0; nf < 4; ++nf)
                    mma16816(acc[mf][nf],
                             af[mf][0], af[mf][1], af[mf][2], af[mf][3],
                             bf[nf][0], bf[nf][1]);
        }
        __syncthreads();
    }

    // ---- epilogue: bias add + scatter to g_gpre[dir][tok][g]
    const int mW = mBase + warpM * 64 + (lane >> 2);
    const int nW = nBase + warpN * 32 + ((lane & 3) << 1);
#pragma unroll
    for (int nf = 0; nf < 4; ++nf) {
        int n = nW + nf * 8;
        float bias0 = bi[n] + bh[n];
        float bias1 = bi[n + 1] + bh[n + 1];
        int dirr = n >> 9;
        int g    = n & 511;
        float* gp = g_gpre + (size_t)dirr * (size_t)total * 512 + g;
#pragma unroll
        for (int mf = 0; mf < 4; ++mf) {
            int m0 = mW + mf * 16;
            if (m0 < total) {
                float2 v = make_float2(acc[mf][nf][0] + bias0, acc[mf][nf][1] + bias1);
                *reinterpret_cast<float2*>(gp + (size_t)m0 * 512) = v;
            }
            int m1 = m0 + 8;
            if (m1 < total) {
                float2 v = make_float2(acc[mf][nf][2] + bias0, acc[mf][nf][3] + bias1);
                *reinterpret_cast<float2*>(gp + (size_t)m1 * 512) = v;
            }
        }
    }
}

// ------------------------------------------------------------- recurrence ---
__device__ __forceinline__ float sigf(float x)
{
    return __fdividef(1.0f, 1.0f + __expf(-x));
}
__device__ __forceinline__ float tanhfast(float x)
{
    x = fminf(fmaxf(x, -12.0f), 12.0f);
    float e = __expf(2.0f * x);
    return __fdividef(e - 1.0f, e + 1.0f);
}

// 128 CTAs: blockIdx.x = dir*64 + b. 256 threads, 2 gates/thread (tid, tid+256).
// W_hh fully register-resident: k<64 fp32 f32x2 pairs, k>=64 fp16 half2.
// SMEM only holds h (fp32 + fp16 mirrors), z exchange, and offsets.
__global__ __launch_bounds__(256, 1)
void rec_kernel(const float* __restrict__ Whh_all,
                const float* __restrict__ h0,
                const float* __restrict__ c0,
                float* __restrict__ dout,
                int total, int T, int layer)
{
    __shared__ __align__(16) float  hs[128];
    __shared__ __align__(16) __half hsh[64];
    __shared__ float zs[512];
    __shared__ int   offs[TMAX];

    const int tid = threadIdx.x;
    const int dir = blockIdx.x >> 6;
    const int b   = blockIdx.x & 63;
    const int kix = 2 * layer + dir;

    const float* gpd = g_gpre + (size_t)dir * (size_t)total * 512;
    const float* W   = Whh_all + (size_t)kix * 512 * 128;

    for (int i = tid; i < T; i += 256) offs[i] = g_offsets[i];

    // k < 64 -> fp32 f32x2 register pairs (2 gates x 32 pairs)
    ull wr[2][32];
#pragma unroll
    for (int e = 0; e < 2; ++e) {
        const float* wg = &W[(tid + 256 * e) * 128];
#pragma unroll
        for (int p = 0; p < 32; ++p) {
            float2 wv = *reinterpret_cast<const float2*>(&wg[2 * p]);
            wr[e][p] = packf2(wv.x, wv.y);
        }
    }
    // k >= 64 -> fp16 half2 registers (2 gates x 32 half2)
    unsigned int whr[2][32];
#pragma unroll
    for (int e = 0; e < 2; ++e) {
        const float* wg = &W[(tid + 256 * e) * 128 + 64];
#pragma unroll
        for (int c = 0; c < 8; ++c) {
            float4 w0 = *reinterpret_cast<const float4*>(&wg[c * 8]);
            float4 w1 = *reinterpret_cast<const float4*>(&wg[c * 8 + 4]);
            whr[e][c * 4 + 0] = h2u(__floats2half2_rn(w0.x, w0.y));
            whr[e][c * 4 + 1] = h2u(__floats2half2_rn(w0.z, w0.w));
            whr[e][c * 4 + 2] = h2u(__floats2half2_rn(w1.x, w1.y));
            whr[e][c * 4 + 3] = h2u(__floats2half2_rn(w1.z, w1.w));
        }
    }

    float creg = 0.f;
    if (tid < 128) {
        float hv = h0[(size_t)kix * 8192 + b * 128 + tid];
        hs[tid] = hv;
        if (tid >= 64) hsh[tid - 64] = __float2half_rn(hv);
        creg = c0[(size_t)kix * 8192 + b * 128 + tid];
    }
    __syncthreads();

    const int  len = g_len[b];
    const bool fwd = (dir == 0);

    int   tok = offs[fwd ? 0 : (len - 1)] + b;
    float gcur0 = gpd[(size_t)tok * 512 + tid];
    float gcur1 = gpd[(size_t)tok * 512 + tid + 256];

    const double2* h2p = reinterpret_cast<const double2*>(hs);
    const uint4*   hhp = reinterpret_cast<const uint4*>(hsh);
    const __half2  hzero = __floats2half2_rn(0.f, 0.f);

    for (int s = 0; s < len; ++s) {
        int   toknext = 0;
        float gnext0 = 0.f, gnext1 = 0.f;
        if (s + 1 < len) {
            int tn  = fwd ? (s + 1) : (len - 2 - s);
            toknext = offs[tn] + b;
            gnext0  = gpd[(size_t)toknext * 512 + tid];
            gnext1  = gpd[(size_t)toknext * 512 + tid + 256];
        }

        float z[2];
#pragma unroll
        for (int e = 0; e < 2; ++e) {
            ull a0 = 0ull, a1 = 0ull;
#pragma unroll
            for (int q = 0; q < 16; ++q) {
                double2 h2 = h2p[q];
                a0 = ffma2(wr[e][2 * q],     __double_as_longlong(h2.x), a0);
                a1 = ffma2(wr[e][2 * q + 1], __double_as_longlong(h2.y), a1);
            }
            __half2 hc0 = hzero, hc1 = hzero;
#pragma unroll
            for (int c = 0; c < 8; ++c) {
                uint4 hv = hhp[c];
                hc0 = __hfma2(uh2(whr[e][c * 4 + 0]), uh2(hv.x), hc0);
                hc1 = __hfma2(uh2(whr[e][c * 4 + 1]), uh2(hv.y), hc1);
                hc0 = __hfma2(uh2(whr[e][c * 4 + 2]), uh2(hv.z), hc0);
                hc1 = __hfma2(uh2(whr[e][c * 4 + 3]), uh2(hv.w), hc1);
            }
            float2 fa = unpackf2(a0);
            float2 fb = unpackf2(a1);
            float2 f0 = __half22float2(hc0);
            float2 f1 = __half22float2(hc1);
            z[e] = ((e == 0) ? gcur0 : gcur1)
                 + (fa.x + fa.y) + (fb.x + fb.y)
                 + (f0.x + f0.y) + (f1.x + f1.y);
        }
        zs[tid]       = z[0];
        zs[tid + 256] = z[1];
        __syncthreads();

        if (tid < 128) {
            float zi = zs[tid];
            float zf = zs[tid + 128];
            float zg = zs[tid + 256];
            float zo = zs[tid + 384];
            float ig = sigf(zi);
            float fg = sigf(zf);
            float gv = tanhfast(zg);
            float og = sigf(zo);
            creg = fg * creg + ig * gv;
            float hv = og * tanhfast(creg);
            hs[tid] = hv;
            if (tid >= 64) hsh[tid - 64] = __float2half_rn(hv);
            if (layer == 0)
                g_out1h[(size_t)tok * 256 + dir * 128 + tid] = __float2half_rn(hv);
            else
                dout[(size_t)tok * 256 + dir * 128 + tid] = hv;
        }
        __syncthreads();

        gcur0 = gnext0;
        gcur1 = gnext1;
        tok   = toknext;
    }

    if (tid < 128) {
        float* hn = dout + (size_t)total * 256 + (size_t)kix * 8192 + (size_t)b * 128;
        float* cn = hn + 4 * 64 * 128;
        hn[tid] = hs[tid];
        cn[tid] = creg;
    }
}

// ---------------------------------------------------------------- launch ----
extern "C" void kernel_launch(void* const* d_in, const int* in_sizes, int n_in,
                              void* d_out, int out_size)
{
    const float* input       = (const float*)d_in[0];
    const int*   batch_sizes = (const int*)  d_in[1];
    const float* h0          = (const float*)d_in[2];
    const float* c0          = (const float*)d_in[3];
    const float* W_ih        = (const float*)d_in[4];
    const float* W_hh        = (const float*)d_in[5];
    const float* b_ih        = (const float*)d_in[6];
    const float* b_hh        = (const float*)d_in[7];
    float* out = (float*)d_out;

    int T     = in_sizes[1];
    int total = in_sizes[0] / 256;
    if (total > TOTAL_MAX) total = TOTAL_MAX;
    if (T > TMAX) T = TMAX;

    const int GEMM_SMEM = 2 * (2 * 128 * AK) * 2;                // 73728 B
    cudaFuncSetAttribute(gemm_hmma, cudaFuncAttributeMaxDynamicSharedMemorySize, GEMM_SMEM);

    setup_kernel<<<1, 1024>>>(batch_sizes, T);

    // fp16 prepass: layer-0 A and all W_ih
    __half* dA16;   cudaGetSymbolAddress((void**)&dA16, g_A16);
    __half* dW16;   cudaGetSymbolAddress((void**)&dW16, g_W16);
    __half* dOut1h; cudaGetSymbolAddress((void**)&dOut1h, g_out1h);
    {
        int n4a = in_sizes[0] / 4;
        int n4w = in_sizes[4] / 4;
        cvt_kernel<<<(n4a + 255) / 256, 256>>>(input, dA16, n4a);
        cvt_kernel<<<(n4w + 255) / 256, 256>>>(W_ih, dW16, n4w);
    }

    dim3 ggrid((total + 127) / 128, 8);
    // layer 0
    gemm_hmma<<<ggrid, 256, GEMM_SMEM>>>(dA16, b_ih, b_hh, total, 0);
    rec_kernel<<<128, 256>>>(W_hh, h0, c0, out, total, T, 0);
    // layer 1
    gemm_hmma<<<ggrid, 256, GEMM_SMEM>>>(dOut1h, b_ih, b_hh, total, 1);
    rec_kernel<<<128, 256>>>(W_hh, h0, c0, out, total, T, 1);
}